// round 13
// baseline (speedup 1.0000x reference)
#include <cuda_runtime.h>
#include <cstdint>
#include <cstddef>

#define NB      8
#define NPTS    16384
#define KNB     32
#define CLEN    32
#define PBLK    128

// ----------------- global scratch -----------------
__device__ float  g_flat[(size_t)NB * NPTS * 64];   // point-major gated features
__device__ float  g_xatt[NB * NPTS];
__device__ int    g_start[2048];
__device__ float2 g_mm[2048];       // (m0,m1) per curve
__device__ double g_part[PBLK][4];  // bar1: m0,m1,m0^2,m1^2
__device__ double g_part2[PBLK][5]; // bar2: Lk,Qk,lp,lp^2,lp*Lk
__device__ float  g_stage[(size_t)2048 * CLEN * 64];
__device__ unsigned int g_barcnt;

__device__ __forceinline__ float wredsum(float v) {
#pragma unroll
    for (int o = 16; o; o >>= 1) v += __shfl_xor_sync(0xffffffffu, v, o);
    return v;
}

__device__ __forceinline__ void bar_arrive() {
    // caller guarantees a preceding __syncthreads so all block writes are done
    if (threadIdx.x == 0) {
        __threadfence();
        atomicAdd(&g_barcnt, 1u);
    }
}

__device__ __forceinline__ void bar_poll(unsigned target) {
    if (threadIdx.x == 0) {
        unsigned v;
        do {
            asm volatile("ld.global.acquire.gpu.u32 %0, [%1];" : "=r"(v) : "l"(&g_barcnt));
        } while (v < target);
    }
    __syncthreads();
}

// gate pair for curve (b,j) given that batch's raw momentum values
__device__ __forceinline__ void gates_for(const float2* mr, int jj,
                                          float mean0, float is0, float mean1, float is1,
                                          float mg0, float mg1, float mb0, float mb1,
                                          float& gaV, float& gbV) {
    int p0 = 2 * jj, p1 = p0 + 1;
    int q0 = p0 & 255, o0 = p0 >> 8, q1 = p1 & 255, o1 = p1 >> 8;
    float2 A = mr[q0];
    float z0 = (A.x - mean0) * is0 * mg0 + mb0;
    float z1 = (A.y - mean1) * is1 * mg1 + mb1;
    float mx = fmaxf(z0, z1);
    float e0 = expf(z0 - mx), e1 = expf(z1 - mx);
    gaV = ((o0 == 0) ? e0 : e1) / (e0 + e1);
    float2 B = mr[q1];
    z0 = (B.x - mean0) * is0 * mg0 + mb0;
    z1 = (B.y - mean1) * is1 * mg1 + mb1;
    mx = fmaxf(z0, z1);
    e0 = expf(z0 - mx); e1 = expf(z1 - mx);
    gbV = ((o1 == 0) ? e0 : e1) / (e0 + e1);
}

// ----------------- K1: gate + transpose -----------------
__global__ void __launch_bounds__(512, 4) k_prep(const float* __restrict__ x,
                                                 const float* __restrict__ attw) {
    __shared__ float sx[64][129];
    __shared__ float satt[128];
    __shared__ float swa[64];
    int t = threadIdx.x;                 // 512 threads
    int tile = blockIdx.x;               // 8 * 128
    int b = tile >> 7, p0 = (tile & 127) << 7;

    if (t < 64) swa[t] = attw[t];
    for (int i = t; i < 64 * 128; i += 512) {
        int c = i >> 7, p = i & 127;
        sx[c][p] = x[((size_t)(b * 64 + c) << 14) + p0 + p];
    }
    __syncthreads();
    if (t < 128) {
        float s = 0.f;
#pragma unroll
        for (int c = 0; c < 64; c++) s += sx[c][t] * swa[c];
        float a = 1.f / (1.f + expf(-s));
        satt[t] = a;
        g_xatt[((size_t)b << 14) + p0 + t] = a;
    }
    __syncthreads();
    for (int i = t; i < 128 * 64; i += 512) {
        int p = i >> 6, c = i & 63;
        g_flat[(((size_t)b << 14) + (size_t)(p0 + p)) * 64 + c] = sx[c][p] * satt[p];
    }
    if (tile == 0 && t == 0) g_barcnt = 0u;
}

// ----------------- K2: exact top-256 via histogram threshold + small bitonic -----------------
__global__ void __launch_bounds__(1024, 1) k_topk() {
    __shared__ int hist[2048];
    __shared__ unsigned long long cand[4096];
    __shared__ int csum[32];
    __shared__ int s_cnt, s_B;
    int b = blockIdx.x, t = threadIdx.x;
    int w = t >> 5, lane = t & 31;

    for (int i = t; i < 2048; i += 1024) hist[i] = 0;
    if (t == 0) s_cnt = 0;
    __syncthreads();
    for (int i = t; i < NPTS; i += 1024) {
        unsigned u = __float_as_uint(g_xatt[((size_t)b << 14) + i]);  // (0,1] positive
        atomicAdd(&hist[u >> 19], 1);
    }
    __syncthreads();
    {
        int acc = 0;
        for (int i = lane; i < 64; i += 32) acc += hist[w * 64 + i];
#pragma unroll
        for (int o = 16; o; o >>= 1) acc += __shfl_xor_sync(0xffffffffu, acc, o);
        if (lane == 0) csum[w] = acc;
    }
    __syncthreads();
    if (t == 0) {
        int accum = 0, wsel = 0;
        for (int ww = 31; ww >= 0; ww--) {
            if (accum + csum[ww] >= 256) { wsel = ww; break; }
            accum += csum[ww];
        }
        int B = wsel * 64;
        for (int bkt = wsel * 64 + 63; bkt >= wsel * 64; bkt--) {
            accum += hist[bkt];
            if (accum >= 256) { B = bkt; break; }
        }
        s_B = B;
    }
    __syncthreads();
    int B = s_B;
    for (int i = t; i < NPTS; i += 1024) {
        unsigned u = __float_as_uint(g_xatt[((size_t)b << 14) + i]);
        if ((int)(u >> 19) >= B) {
            int p = atomicAdd(&s_cnt, 1);
            if (p < 4096)
                cand[p] = ((unsigned long long)u << 32) | (unsigned)(0xFFFFFFFFu - (unsigned)i);
        }
    }
    __syncthreads();
    int n = s_cnt; if (n > 4096) n = 4096;
    for (int i = t; i < 4096; i += 1024)
        if (i >= n) cand[i] = 0ull;
    for (int size = 2; size <= 4096; size <<= 1) {
        for (int stride = size >> 1; stride > 0; stride >>= 1) {
            __syncthreads();
            for (int i = t; i < 2048; i += 1024) {
                int pos = 2 * i - (i & (stride - 1));
                unsigned long long a = cand[pos], bb = cand[pos + stride];
                bool asc = (pos & size) != 0;
                bool sw = asc ? (a > bb) : (a < bb);
                if (sw) { cand[pos] = bb; cand[pos + stride] = a; }
            }
        }
    }
    __syncthreads();
    if (t < 256) {
        unsigned low = (unsigned)(cand[t] & 0xFFFFFFFFull);
        int p = (int)(0xFFFFFFFFu - low);
        g_start[(b << 8) + t] = (b << 14) + p;
    }
}

// ----------------- K3: persistent curve walk, gather+pass in barrier shadow -----------------
struct SW {
    float  cur[16][64], pre[16][64];
    float  w1[64], w2[64], mw[256];
    float  lpv[16][32], Pk[16][32], Rk[16][32], Nk[16][32];
    int    pts[16][32];
    float  hpart[16][4][32];
    float  red[16][2][4];
    float  mm0[16], mm1[16], w2c[16], w2p[16];
    float  lpre[16], ga[16], gb[16];
    float  Lk[16], Qk[16];
    int    fcur[16], sel[16];
    float  ag, ab, mg0, mg1, mb0, mb1;
    float  bnf[4];
    double bns[4], bns2[5];
};

__global__ void __launch_bounds__(1024, 1) k_walk(
    const int* __restrict__ idx,
    const float* __restrict__ agw, const float* __restrict__ agg, const float* __restrict__ agb,
    const float* __restrict__ mwi, const float* __restrict__ mgi, const float* __restrict__ mbi)
{
    __shared__ SW sm;
    extern __shared__ float dyn[];
    float*  pv  = dyn;                                  // [16][32][65]
    float4* bk4 = (float4*)(dyn + 16 * 32 * 65);        // [16][64] (w1,cur,pre,-)

    int t = threadIdx.x;
    int s = t >> 6, t64 = t & 63, half = t64 >> 5, lane = t & 31, c = t64;
    int gi = (blockIdx.x << 4) + s;
    int b = gi >> 8, j = gi & 255, boff = b << 14;
    unsigned epoch = 1;

    if (t < 64) { sm.w1[t] = agw[t]; sm.w2[t] = agw[64 + t]; }
    if (t >= 256 && t < 512) sm.mw[t - 256] = mwi[t - 256];
    if (t == 0) {
        sm.ag = agg[0]; sm.ab = agb[0];
        sm.mg0 = mgi[0]; sm.mg1 = mgi[1]; sm.mb0 = mbi[0]; sm.mb1 = mbi[1];
    }
    if (t64 == 0) sm.fcur[s] = g_start[gi];
    __syncthreads();

    for (int step = 0; step < CLEN; step++) {
        // ===== segment 1 (SHORT): momentum dots + publish, then ARRIVE bar1 =====
        int fc = sm.fcur[s];
        float cu, pm;
        if (step == 0) {
            pm = g_flat[((size_t)fc << 6) + c];
            cu = 0.f;
            sm.cur[s][c] = 0.f;
            sm.pre[s][c] = pm;
        } else {
            cu = sm.cur[s][c];
            pm = sm.pre[s][c];
        }
        bk4[s * 64 + c] = make_float4(sm.w1[c], cu, pm, 0.f);
        {   // momentum raw dots + w2 dots
            float r0 = sm.mw[c] * cu + sm.mw[64 + c] * pm;
            float r1 = sm.mw[128 + c] * cu + sm.mw[192 + c] * pm;
            float r2 = sm.w2[c] * cu;
            float r3 = sm.w2[c] * pm;
            r0 = wredsum(r0); r1 = wredsum(r1); r2 = wredsum(r2); r3 = wredsum(r3);
            if (lane == 0) {
                float* rr = sm.red[s][half];
                rr[0] = r0; rr[1] = r1; rr[2] = r2; rr[3] = r3;
            }
        }
        if (t64 < 32) sm.pts[s][t64] = idx[(size_t)fc * KNB + t64] + boff;
        __syncthreads();   // S1 (red + pts visible)
        if (t64 == 0) {
            float m0 = sm.red[s][0][0] + sm.red[s][1][0];
            float m1 = sm.red[s][0][1] + sm.red[s][1][1];
            sm.mm0[s] = m0; sm.mm1[s] = m1;
            g_mm[gi] = make_float2(m0, m1);
            sm.w2c[s] = sm.red[s][0][2] + sm.red[s][1][2];
            sm.w2p[s] = sm.red[s][0][3] + sm.red[s][1][3];
        }
        __syncthreads();   // S2 (mm visible for publish)
        // publish bar1 partials: m0, m1, m0^2, m1^2 (2 full warps)
        if (t < 64) {
            int q = t >> 4, ss = t & 15;
            float m0 = sm.mm0[ss], m1 = sm.mm1[ss];
            double v = (q == 0) ? (double)m0 : (q == 1) ? (double)m1 :
                       (q == 2) ? (double)m0 * m0 : (double)m1 * m1;
#pragma unroll
            for (int o = 8; o; o >>= 1) v += __shfl_xor_sync(0xffffffffu, v, o, 16);
            if ((t & 15) == 0) g_part[blockIdx.x][q] = v;
        }
        __syncthreads();   // S3 (g_part + g_mm visible before arrival)
        bar_arrive();      // ===== arrive bar1 =====

        // ===== overlap window: gather + heavy per-k pass hide bar1 skew =====
        {
            int kk = t64 >> 4, col = (t64 & 15) << 2;
#pragma unroll
            for (int k0 = 0; k0 < 8; k0++) {
                int k = k0 * 4 + kk;
                int pt = sm.pts[s][k];
                float4 v4 = __ldg((const float4*)&g_flat[((size_t)pt << 6) + col]);
                float* dst = &pv[(s * 32 + k) * 65 + col];
                dst[0] = v4.x; dst[1] = v4.y; dst[2] = v4.z; dst[3] = v4.w;
            }
        }
        __syncthreads();   // Sg (pv visible)
        {
            int off = half * 32;
            const float* pvb = &pv[(s * 32 + lane) * 65 + off];
            const float4* bk = &bk4[s * 64 + off];
            float accL = 0.f, accP = 0.f, accR = 0.f, accN = 0.f;
#pragma unroll 8
            for (int cc = 0; cc < 32; cc++) {
                float v = pvb[cc];
                float4 q = bk[cc];
                accL += v * q.x;
                float nb = v - q.y;
                accP += q.y * nb;
                accR += q.z * nb;
                accN += nb * nb;
            }
            if (half == 1) {
                sm.hpart[s][0][lane] = accL;
                sm.hpart[s][1][lane] = accP;
                sm.hpart[s][2][lane] = accR;
                sm.hpart[s][3][lane] = accN;
            }
            __syncthreads();   // S4
            if (t64 < 32) {
                int k = lane;
                float L = accL + sm.hpart[s][0][k];
                sm.lpv[s][k] = L;
                sm.Pk[s][k] = accP + sm.hpart[s][1][k];
                sm.Rk[s][k] = accR + sm.hpart[s][2][k];
                sm.Nk[s][k] = accN + sm.hpart[s][3][k];
                float s1 = wredsum(L);
                float s2 = wredsum(L * L);
                if (k == 0) { sm.Lk[s] = s1; sm.Qk[s] = s2; }
            }
        }
        __syncthreads();   // S5
        bar_poll(PBLK * epoch); epoch++;   // ===== poll bar1 =====

        // ===== BN1: momentum BN + gates + lpre, publish + ARRIVE bar2 =====
        if (t < 128) {   // 4 full warps
            int w = t >> 5, ll = t & 31;
            double a = g_part[ll][w] + g_part[ll + 32][w]
                     + g_part[ll + 64][w] + g_part[ll + 96][w];
#pragma unroll
            for (int o = 16; o; o >>= 1) a += __shfl_xor_sync(0xffffffffu, a, o);
            if (ll == 0) sm.bns[w] = a;
        }
        __syncthreads();   // S6
        if (t64 == 0) {    // per-slot leaders: finalize BN1 redundantly + own gates
            float gaV, gbV;
            if (step == 0) { gaV = 0.f; gbV = 1.f; }
            else {
                double m0 = sm.bns[0] * (1.0 / 2048.0), m1 = sm.bns[1] * (1.0 / 2048.0);
                double v0 = sm.bns[2] * (1.0 / 2048.0) - m0 * m0;
                double v1 = sm.bns[3] * (1.0 / 2048.0) - m1 * m1;
                float mean0 = (float)m0, is0 = (float)(1.0 / sqrt(v0 + 1e-5));
                float mean1 = (float)m1, is1 = (float)(1.0 / sqrt(v1 + 1e-5));
                gates_for(&g_mm[b << 8], j, mean0, is0, mean1, is1,
                          sm.mg0, sm.mg1, sm.mb0, sm.mb1, gaV, gbV);
            }
            sm.ga[s] = gaV; sm.gb[s] = gbV;
            sm.lpre[s] = gaV * sm.w2c[s] + gbV * sm.w2p[s];
        }
        __syncthreads();   // S8
        // publish bar2 partials: Lk, Qk, lp, lp^2, lp*Lk (3 full warps, q==5 dummy)
        if (t < 96) {
            int q = t >> 4, ss = t & 15;
            double v = 0.0;
            if (q < 5) {
                float lp = sm.lpre[ss];
                v = (q == 0) ? (double)sm.Lk[ss] : (q == 1) ? (double)sm.Qk[ss] :
                    (q == 2) ? (double)lp : (q == 3) ? (double)lp * lp
                                          : (double)lp * sm.Lk[ss];
            }
#pragma unroll
            for (int o = 8; o; o >>= 1) v += __shfl_xor_sync(0xffffffffu, v, o, 16);
            if ((t & 15) == 0 && q < 5) g_part2[blockIdx.x][q] = v;
        }
        __syncthreads();   // S9
        bar_arrive();      // ===== arrive bar2 =====

        // ===== overlap window: pre update hides bar2 skew =====
        {
            float po = sm.pre[s][c];
            float pnew = sm.ga[s] * cu + sm.gb[s] * po;
            sm.pre[s][c] = pnew;
            float ac = cu - pnew;
            float r0 = wredsum(ac * ac);
            if (lane == 0) sm.red[s][half][0] = r0;
        }
        bar_poll(PBLK * epoch); epoch++;   // ===== poll bar2 (its sync makes red visible) =====

        // ===== BN2: agent BN + crossover + select =====
        if (t < 160) {   // 5 full warps
            int w = t >> 5, ll = t & 31;
            double a = g_part2[ll][w] + g_part2[ll + 32][w]
                     + g_part2[ll + 64][w] + g_part2[ll + 96][w];
#pragma unroll
            for (int o = 16; o; o >>= 1) a += __shfl_xor_sync(0xffffffffu, a, o);
            if (ll == 0) sm.bns2[w] = a;
        }
        __syncthreads();   // S11
        if (t64 < 32) {
            int k = t64;
            // finalize agent BN redundantly (identical double ops in every thread)
            double S  = sm.bns2[0] + 32.0 * sm.bns2[2];
            double SS = sm.bns2[1] + 2.0 * sm.bns2[4] + 32.0 * sm.bns2[3];
            double meanD = S * (1.0 / 65536.0);
            double varD  = SS * (1.0 / 65536.0) - meanD * meanD;
            float meanA = (float)meanD;
            float stdA  = (float)sqrt(varD + 1e-5);
            float naV = sqrtf(sm.red[s][0][0] + sm.red[s][1][0]);
            float lg = sm.lpv[s][k] + sm.lpre[s];
            float z = (lg - meanA) / stdA * sm.ag + sm.ab;
            float l2 = z;
            if (step > 0) {
                float dotv = (1.f - sm.ga[s]) * sm.Pk[s][k] - sm.gb[s] * sm.Rk[s][k];
                float nbl = sqrtf(sm.Nk[s][k]);
                float dv = fmaxf(naV * nbl, 1e-8f);
                float d = 1.f + dotv / dv;
                d = fminf(fmaxf(d, 0.f), 1.f);
                l2 = z * d;
            }
            float mx = l2;
#pragma unroll
            for (int o = 16; o; o >>= 1) mx = fmaxf(mx, __shfl_xor_sync(0xffffffffu, mx, o));
            float e = expf(l2 - mx);
            float se = wredsum(e);
            float y = e / se;
            unsigned long long key =
                ((unsigned long long)__float_as_uint(y) << 32) | (unsigned)(31 - k);
#pragma unroll
            for (int o = 16; o; o >>= 1) {
                unsigned long long kk = __shfl_xor_sync(0xffffffffu, key, o);
                if (kk > key) key = kk;
            }
            if (k == 0) {
                int sl = 31 - (int)(key & 0xFFFFFFFFull);
                sm.sel[s] = sl;
                sm.fcur[s] = sm.pts[s][sl];
            }
        }
        __syncthreads();   // S13
        {
            float nc = pv[(s * 32 + sm.sel[s]) * 65 + c];
            sm.cur[s][c] = nc;
            g_stage[((size_t)gi * CLEN + step) * 64 + c] = nc;
        }
        // next-iteration S1 orders these pv reads before the next gather writes
    }
}

// ----------------- K4: stage -> out transpose -----------------
__global__ void k_out(float* __restrict__ out) {
    __shared__ float tile[CLEN][65];
    int gi = blockIdx.x, b = gi >> 8, j = gi & 255;
    int t = threadIdx.x;   // 256
    for (int i = t; i < CLEN * 64; i += 256) {
        int st = i >> 6, c = i & 63;
        tile[st][c] = g_stage[((size_t)gi * CLEN + st) * 64 + c];
    }
    __syncthreads();
    for (int i = t; i < 64 * CLEN; i += 256) {
        int c = i >> 5, st = i & 31;
        out[((size_t)(b * 64 + c) * 256 + (size_t)j) * CLEN + st] = tile[st][c];
    }
}

// ----------------- launch -----------------
extern "C" void kernel_launch(void* const* d_in, const int* in_sizes, int n_in,
                              void* d_out, int out_size) {
    const float* x    = (const float*)d_in[0];
    // d_in[1] = xyz (unused by the reference forward)
    const int*   idx  = (const int*)d_in[2];
    const float* attw = (const float*)d_in[3];
    const float* agw  = (const float*)d_in[4];
    const float* agg  = (const float*)d_in[5];
    const float* agb  = (const float*)d_in[6];
    const float* mw   = (const float*)d_in[7];
    const float* mg   = (const float*)d_in[8];
    const float* mb   = (const float*)d_in[9];
    float* out = (float*)d_out;

    const int WALK_DYN = (16 * 32 * 65) * 4 + 16 * 64 * 16;   // pv + bk4
    cudaFuncSetAttribute(k_walk, cudaFuncAttributeMaxDynamicSharedMemorySize, WALK_DYN);

    k_prep<<<NB * 128, 512>>>(x, attw);
    k_topk<<<NB, 1024>>>();
    k_walk<<<PBLK, 1024, WALK_DYN>>>(idx, agw, agg, agb, mw, mg, mb);
    k_out<<<2048, 256>>>(out);
}

// round 16
// speedup vs baseline: 1.0182x; 1.0182x over previous
#include <cuda_runtime.h>
#include <cstdint>
#include <cstddef>

#define NB      8
#define NPTS    16384
#define KNB     32
#define CLEN    32
#define PBLK    128

// ----------------- global scratch -----------------
__device__ float  g_flat[(size_t)NB * NPTS * 64];   // point-major gated features
__device__ float  g_xatt[NB * NPTS];
__device__ int    g_start[2048];
__device__ float2 g_mm[2048];       // (m0,m1) per curve
__device__ double g_part[PBLK][4];  // bar1: m0,m1,m0^2,m1^2
__device__ double g_part2[PBLK][5]; // bar2: Lk,Qk,lp,lp^2,lp*Lk
__device__ unsigned int g_barcnt;

__device__ __forceinline__ float wredsum(float v) {
#pragma unroll
    for (int o = 16; o; o >>= 1) v += __shfl_xor_sync(0xffffffffu, v, o);
    return v;
}

__device__ __forceinline__ void bar_arrive() {
    // caller guarantees a preceding __syncthreads so all block writes are done
    if (threadIdx.x == 0) {
        __threadfence();
        atomicAdd(&g_barcnt, 1u);
    }
}

__device__ __forceinline__ void bar_poll(unsigned target) {
    if (threadIdx.x == 0) {
        unsigned v;
        do {
            asm volatile("ld.global.acquire.gpu.u32 %0, [%1];" : "=r"(v) : "l"(&g_barcnt));
        } while (v < target);
    }
    __syncthreads();
}

// gate pair for curve (b,j) given that batch's raw momentum values
__device__ __forceinline__ void gates_for(const float2* mr, int jj,
                                          float mean0, float is0, float mean1, float is1,
                                          float mg0, float mg1, float mb0, float mb1,
                                          float& gaV, float& gbV) {
    int p0 = 2 * jj, p1 = p0 + 1;
    int q0 = p0 & 255, o0 = p0 >> 8, q1 = p1 & 255, o1 = p1 >> 8;
    float2 A = mr[q0];
    float z0 = (A.x - mean0) * is0 * mg0 + mb0;
    float z1 = (A.y - mean1) * is1 * mg1 + mb1;
    float mx = fmaxf(z0, z1);
    float e0 = expf(z0 - mx), e1 = expf(z1 - mx);
    gaV = ((o0 == 0) ? e0 : e1) / (e0 + e1);
    float2 B = mr[q1];
    z0 = (B.x - mean0) * is0 * mg0 + mb0;
    z1 = (B.y - mean1) * is1 * mg1 + mb1;
    mx = fmaxf(z0, z1);
    e0 = expf(z0 - mx); e1 = expf(z1 - mx);
    gbV = ((o1 == 0) ? e0 : e1) / (e0 + e1);
}

// ----------------- K1: gate + transpose -----------------
__global__ void __launch_bounds__(512, 4) k_prep(const float* __restrict__ x,
                                                 const float* __restrict__ attw) {
    __shared__ float sx[64][129];
    __shared__ float satt[128];
    __shared__ float swa[64];
    int t = threadIdx.x;                 // 512 threads
    int tile = blockIdx.x;               // 8 * 128
    int b = tile >> 7, p0 = (tile & 127) << 7;

    if (t < 64) swa[t] = attw[t];
    for (int i = t; i < 64 * 128; i += 512) {
        int c = i >> 7, p = i & 127;
        sx[c][p] = x[((size_t)(b * 64 + c) << 14) + p0 + p];
    }
    __syncthreads();
    if (t < 128) {
        float s = 0.f;
#pragma unroll
        for (int c = 0; c < 64; c++) s += sx[c][t] * swa[c];
        float a = 1.f / (1.f + expf(-s));
        satt[t] = a;
        g_xatt[((size_t)b << 14) + p0 + t] = a;
    }
    __syncthreads();
    for (int i = t; i < 128 * 64; i += 512) {
        int p = i >> 6, c = i & 63;
        g_flat[(((size_t)b << 14) + (size_t)(p0 + p)) * 64 + c] = sx[c][p] * satt[p];
    }
    if (tile == 0 && t == 0) g_barcnt = 0u;
}

// ----------------- K2: exact top-256 via histogram threshold + small bitonic -----------------
__global__ void __launch_bounds__(1024, 1) k_topk() {
    __shared__ int hist[2048];
    __shared__ unsigned long long cand[4096];
    __shared__ int csum[32];
    __shared__ int s_cnt, s_B;
    int b = blockIdx.x, t = threadIdx.x;
    int w = t >> 5, lane = t & 31;

    for (int i = t; i < 2048; i += 1024) hist[i] = 0;
    if (t == 0) s_cnt = 0;
    __syncthreads();
    for (int i = t; i < NPTS; i += 1024) {
        unsigned u = __float_as_uint(g_xatt[((size_t)b << 14) + i]);  // (0,1] positive
        atomicAdd(&hist[u >> 19], 1);
    }
    __syncthreads();
    {
        int acc = 0;
        for (int i = lane; i < 64; i += 32) acc += hist[w * 64 + i];
#pragma unroll
        for (int o = 16; o; o >>= 1) acc += __shfl_xor_sync(0xffffffffu, acc, o);
        if (lane == 0) csum[w] = acc;
    }
    __syncthreads();
    if (t == 0) {
        int accum = 0, wsel = 0;
        for (int ww = 31; ww >= 0; ww--) {
            if (accum + csum[ww] >= 256) { wsel = ww; break; }
            accum += csum[ww];
        }
        int B = wsel * 64;
        for (int bkt = wsel * 64 + 63; bkt >= wsel * 64; bkt--) {
            accum += hist[bkt];
            if (accum >= 256) { B = bkt; break; }
        }
        s_B = B;
    }
    __syncthreads();
    int B = s_B;
    for (int i = t; i < NPTS; i += 1024) {
        unsigned u = __float_as_uint(g_xatt[((size_t)b << 14) + i]);
        if ((int)(u >> 19) >= B) {
            int p = atomicAdd(&s_cnt, 1);
            if (p < 4096)
                cand[p] = ((unsigned long long)u << 32) | (unsigned)(0xFFFFFFFFu - (unsigned)i);
        }
    }
    __syncthreads();
    int n = s_cnt; if (n > 4096) n = 4096;
    for (int i = t; i < 4096; i += 1024)
        if (i >= n) cand[i] = 0ull;
    for (int size = 2; size <= 4096; size <<= 1) {
        for (int stride = size >> 1; stride > 0; stride >>= 1) {
            __syncthreads();
            for (int i = t; i < 2048; i += 1024) {
                int pos = 2 * i - (i & (stride - 1));
                unsigned long long a = cand[pos], bb = cand[pos + stride];
                bool asc = (pos & size) != 0;
                bool sw = asc ? (a > bb) : (a < bb);
                if (sw) { cand[pos] = bb; cand[pos + stride] = a; }
            }
        }
    }
    __syncthreads();
    if (t < 256) {
        unsigned low = (unsigned)(cand[t] & 0xFFFFFFFFull);
        int p = (int)(0xFFFFFFFFu - low);
        g_start[(b << 8) + t] = (b << 14) + p;
    }
}

// ----------------- K3: persistent curve walk (R12 structure, trimmed) -----------------
struct SW {
    float  cur[16][64], pre[16][64];
    float  w1[64], w2[64], mw[256];
    float  lpv[16][32], Pk[16][32], Rk[16][32], Nk[16][32];
    int    pts[16][32];
    float  hpart[16][4][32];
    float  red[16][2][4];
    float  w2c[16], w2p[16];
    float  lpre[16], ga[16], gb[16];
    float  Lk[16], Qk[16];
    int    fcur[16], sel[16];
    float  ag, ab, mg0, mg1, mb0, mb1;
    double bns[4], bns2[5];
};

__global__ void __launch_bounds__(1024, 1) k_walk(
    const int* __restrict__ idx,
    const float* __restrict__ agw, const float* __restrict__ agg, const float* __restrict__ agb,
    const float* __restrict__ mwi, const float* __restrict__ mgi, const float* __restrict__ mbi,
    float* __restrict__ out)
{
    __shared__ SW sm;
    extern __shared__ float dyn[];
    float*  pv  = dyn;                                  // [16][32][65]
    float4* bk4 = (float4*)(dyn + 16 * 32 * 65);        // [16][64] (w1,cur,pre,-)

    int t = threadIdx.x;
    int s = t >> 6, t64 = t & 63, half = t64 >> 5, lane = t & 31, c = t64;
    int gi = (blockIdx.x << 4) + s;
    int b = gi >> 8, j = gi & 255, boff = b << 14;
    unsigned epoch = 1;

    if (t < 64) { sm.w1[t] = agw[t]; sm.w2[t] = agw[64 + t]; }
    if (t >= 256 && t < 512) sm.mw[t - 256] = mwi[t - 256];
    if (t == 0) {
        sm.ag = agg[0]; sm.ab = agb[0];
        sm.mg0 = mgi[0]; sm.mg1 = mgi[1]; sm.mb0 = mbi[0]; sm.mb1 = mbi[1];
    }
    if (t64 == 0) sm.fcur[s] = g_start[gi];
    __syncthreads();

    for (int step = 0; step < CLEN; step++) {
        // ===== segment 1: momentum dots + gather + publish, then ARRIVE bar1 =====
        int fc = sm.fcur[s];
        float cu, pm;
        if (step == 0) {
            pm = g_flat[((size_t)fc << 6) + c];
            cu = 0.f;
            sm.cur[s][c] = 0.f;
            sm.pre[s][c] = pm;
        } else {
            cu = sm.cur[s][c];
            pm = sm.pre[s][c];
        }
        bk4[s * 64 + c] = make_float4(sm.w1[c], cu, pm, 0.f);
        {   // momentum raw dots + w2 dots
            float r0 = sm.mw[c] * cu + sm.mw[64 + c] * pm;
            float r1 = sm.mw[128 + c] * cu + sm.mw[192 + c] * pm;
            float r2 = sm.w2[c] * cu;
            float r3 = sm.w2[c] * pm;
            r0 = wredsum(r0); r1 = wredsum(r1); r2 = wredsum(r2); r3 = wredsum(r3);
            if (lane == 0) {
                float* rr = sm.red[s][half];
                rr[0] = r0; rr[1] = r1; rr[2] = r2; rr[3] = r3;
            }
        }
        if (t64 < 32) sm.pts[s][t64] = idx[(size_t)fc * KNB + t64] + boff;
        __syncthreads();   // S1 (red + pts visible)
        if (t64 == 0) {    // leader: own-curve outputs for other blocks / BN1
            float m0 = sm.red[s][0][0] + sm.red[s][1][0];
            float m1 = sm.red[s][0][1] + sm.red[s][1][1];
            g_mm[gi] = make_float2(m0, m1);
            sm.w2c[s] = sm.red[s][0][2] + sm.red[s][1][2];
            sm.w2p[s] = sm.red[s][0][3] + sm.red[s][1][3];
        }
        // gather 32 neighbor rows (float4 loads, coalesced)
        {
            int kk = t64 >> 4, col = (t64 & 15) << 2;
#pragma unroll
            for (int k0 = 0; k0 < 8; k0++) {
                int k = k0 * 4 + kk;
                int pt = sm.pts[s][k];
                float4 v4 = __ldg((const float4*)&g_flat[((size_t)pt << 6) + col]);
                float* dst = &pv[(s * 32 + k) * 65 + col];
                dst[0] = v4.x; dst[1] = v4.y; dst[2] = v4.z; dst[3] = v4.w;
            }
        }
        // publish bar1 partials directly from red (bitwise same as leader's m)
        if (t < 64) {
            int q = t >> 4, ss = t & 15;
            float m0 = sm.red[ss][0][0] + sm.red[ss][1][0];
            float m1 = sm.red[ss][0][1] + sm.red[ss][1][1];
            double v = (q == 0) ? (double)m0 : (q == 1) ? (double)m1 :
                       (q == 2) ? (double)m0 * m0 : (double)m1 * m1;
#pragma unroll
            for (int o = 8; o; o >>= 1) v += __shfl_xor_sync(0xffffffffu, v, o, 16);
            if ((t & 15) == 0) g_part[blockIdx.x][q] = v;
        }
        __syncthreads();   // S3 (g_part + g_mm + pv visible before arrival)
        bar_arrive();      // ===== arrive bar1 =====

        // ===== overlap window: heavy per-k pass hides bar1 skew =====
        {
            int off = half * 32;
            const float* pvb = &pv[(s * 32 + lane) * 65 + off];
            const float4* bk = &bk4[s * 64 + off];
            float accL = 0.f, accP = 0.f, accR = 0.f, accN = 0.f;
#pragma unroll 8
            for (int cc = 0; cc < 32; cc++) {
                float v = pvb[cc];
                float4 q = bk[cc];
                accL += v * q.x;
                float nb = v - q.y;
                accP += q.y * nb;
                accR += q.z * nb;
                accN += nb * nb;
            }
            if (half == 1) {
                sm.hpart[s][0][lane] = accL;
                sm.hpart[s][1][lane] = accP;
                sm.hpart[s][2][lane] = accR;
                sm.hpart[s][3][lane] = accN;
            }
            __syncthreads();   // S4
            if (t64 < 32) {
                int k = lane;
                float L = accL + sm.hpart[s][0][k];
                sm.lpv[s][k] = L;
                sm.Pk[s][k] = accP + sm.hpart[s][1][k];
                sm.Rk[s][k] = accR + sm.hpart[s][2][k];
                sm.Nk[s][k] = accN + sm.hpart[s][3][k];
                float s1 = wredsum(L);
                float s2 = wredsum(L * L);
                if (k == 0) { sm.Lk[s] = s1; sm.Qk[s] = s2; }
            }
        }
        __syncthreads();   // S5
        bar_poll(PBLK * epoch); epoch++;   // ===== poll bar1 =====

        // ===== BN1: momentum BN + gates + lpre, publish + ARRIVE bar2 =====
        if (t < 128) {   // 4 full warps
            int w = t >> 5, ll = t & 31;
            double a = g_part[ll][w] + g_part[ll + 32][w]
                     + g_part[ll + 64][w] + g_part[ll + 96][w];
#pragma unroll
            for (int o = 16; o; o >>= 1) a += __shfl_xor_sync(0xffffffffu, a, o);
            if (ll == 0) sm.bns[w] = a;
        }
        __syncthreads();   // S6
        if (t64 == 0) {    // per-slot leaders: finalize BN1 redundantly + own gates
            float gaV, gbV;
            if (step == 0) { gaV = 0.f; gbV = 1.f; }
            else {
                double m0 = sm.bns[0] * (1.0 / 2048.0), m1 = sm.bns[1] * (1.0 / 2048.0);
                double v0 = sm.bns[2] * (1.0 / 2048.0) - m0 * m0;
                double v1 = sm.bns[3] * (1.0 / 2048.0) - m1 * m1;
                float mean0 = (float)m0, is0 = (float)(1.0 / sqrt(v0 + 1e-5));
                float mean1 = (float)m1, is1 = (float)(1.0 / sqrt(v1 + 1e-5));
                gates_for(&g_mm[b << 8], j, mean0, is0, mean1, is1,
                          sm.mg0, sm.mg1, sm.mb0, sm.mb1, gaV, gbV);
            }
            sm.ga[s] = gaV; sm.gb[s] = gbV;
            sm.lpre[s] = gaV * sm.w2c[s] + gbV * sm.w2p[s];
        }
        __syncthreads();   // S8
        // publish bar2 partials: Lk, Qk, lp, lp^2, lp*Lk (3 full warps, q==5 dummy)
        if (t < 96) {
            int q = t >> 4, ss = t & 15;
            double v = 0.0;
            if (q < 5) {
                float lp = sm.lpre[ss];
                v = (q == 0) ? (double)sm.Lk[ss] : (q == 1) ? (double)sm.Qk[ss] :
                    (q == 2) ? (double)lp : (q == 3) ? (double)lp * lp
                                          : (double)lp * sm.Lk[ss];
            }
#pragma unroll
            for (int o = 8; o; o >>= 1) v += __shfl_xor_sync(0xffffffffu, v, o, 16);
            if ((t & 15) == 0 && q < 5) g_part2[blockIdx.x][q] = v;
        }
        __syncthreads();   // S9
        bar_arrive();      // ===== arrive bar2 =====

        // ===== overlap window: pre update + d/lg precompute hide bar2 skew =====
        {
            float po = sm.pre[s][c];
            float pnew = sm.ga[s] * cu + sm.gb[s] * po;
            sm.pre[s][c] = pnew;
            float ac = cu - pnew;
            float r0 = wredsum(ac * ac);
            if (lane == 0) sm.red[s][half][0] = r0;
        }
        __syncthreads();   // W1 (red visible for na)
        float dpre = 1.f, lgpre = 0.f;
        if (t64 < 32) {
            int k = t64;
            lgpre = sm.lpv[s][k] + sm.lpre[s];
            if (step > 0) {
                float naV = sqrtf(sm.red[s][0][0] + sm.red[s][1][0]);
                float dotv = (1.f - sm.ga[s]) * sm.Pk[s][k] - sm.gb[s] * sm.Rk[s][k];
                float nbl = sqrtf(sm.Nk[s][k]);
                float dv = fmaxf(naV * nbl, 1e-8f);
                float d = 1.f + dotv / dv;
                dpre = fminf(fmaxf(d, 0.f), 1.f);
            }
        }
        bar_poll(PBLK * epoch); epoch++;   // ===== poll bar2 =====

        // ===== BN2: agent BN + select =====
        if (t < 160) {   // 5 full warps
            int w = t >> 5, ll = t & 31;
            double a = g_part2[ll][w] + g_part2[ll + 32][w]
                     + g_part2[ll + 64][w] + g_part2[ll + 96][w];
#pragma unroll
            for (int o = 16; o; o >>= 1) a += __shfl_xor_sync(0xffffffffu, a, o);
            if (ll == 0) sm.bns2[w] = a;
        }
        __syncthreads();   // S11
        if (t64 < 32) {
            int k = t64;
            // finalize agent BN redundantly (identical double ops in every thread)
            double S  = sm.bns2[0] + 32.0 * sm.bns2[2];
            double SS = sm.bns2[1] + 2.0 * sm.bns2[4] + 32.0 * sm.bns2[3];
            double meanD = S * (1.0 / 65536.0);
            double varD  = SS * (1.0 / 65536.0) - meanD * meanD;
            float meanA = (float)meanD;
            float stdA  = (float)sqrt(varD + 1e-5);
            float z = (lgpre - meanA) / stdA * sm.ag + sm.ab;
            float l2 = z * dpre;          // dpre==1 at step 0
            float mx = l2;
#pragma unroll
            for (int o = 16; o; o >>= 1) mx = fmaxf(mx, __shfl_xor_sync(0xffffffffu, mx, o));
            float e = expf(l2 - mx);
            float se = wredsum(e);
            float y = e / se;
            unsigned long long key =
                ((unsigned long long)__float_as_uint(y) << 32) | (unsigned)(31 - k);
#pragma unroll
            for (int o = 16; o; o >>= 1) {
                unsigned long long kk = __shfl_xor_sync(0xffffffffu, key, o);
                if (kk > key) key = kk;
            }
            if (k == 0) {
                int sl = 31 - (int)(key & 0xFFFFFFFFull);
                sm.sel[s] = sl;
                sm.fcur[s] = sm.pts[s][sl];
            }
        }
        __syncthreads();   // S13
        {
            float nc = pv[(s * 32 + sm.sel[s]) * 65 + c];
            sm.cur[s][c] = nc;
            // direct final-layout write: out[b][c][j][step]
            out[((size_t)(b * 64 + c) * 256 + (size_t)j) * CLEN + step] = nc;
        }
        // next-iteration S1 orders these pv reads before the next gather writes
    }
}

// ----------------- launch -----------------
extern "C" void kernel_launch(void* const* d_in, const int* in_sizes, int n_in,
                              void* d_out, int out_size) {
    const float* x    = (const float*)d_in[0];
    // d_in[1] = xyz (unused by the reference forward)
    const int*   idx  = (const int*)d_in[2];
    const float* attw = (const float*)d_in[3];
    const float* agw  = (const float*)d_in[4];
    const float* agg  = (const float*)d_in[5];
    const float* agb  = (const float*)d_in[6];
    const float* mw   = (const float*)d_in[7];
    const float* mg   = (const float*)d_in[8];
    const float* mb   = (const float*)d_in[9];
    float* out = (float*)d_out;

    const int WALK_DYN = (16 * 32 * 65) * 4 + 16 * 64 * 16;   // pv + bk4
    cudaFuncSetAttribute(k_walk, cudaFuncAttributeMaxDynamicSharedMemorySize, WALK_DYN);

    k_prep<<<NB * 128, 512>>>(x, attw);
    k_topk<<<NB, 1024>>>();
    k_walk<<<PBLK, 1024, WALK_DYN>>>(idx, agw, agg, agb, mw, mg, mb, out);
}